// round 10
// baseline (speedup 1.0000x reference)
#include <cuda_runtime.h>
#include <cuda_bf16.h>
#include <cstdint>
#include <cstring>

#define D_IN      512
#define NUM_CODES 2048
#define D_OUT     256
#define MAX_ROWS  100096   // ceil(100000/128)*128

typedef unsigned long long u64;

// int8 quantization scales (fixed; h ~ N(0,1), cb elements ~ N(0,1/512))
#define INV_SH 20.0f      // s_h = 0.05
#define INV_SC 500.0f     // s_c = 0.002
#define SC2    2.0e-4f    // 2 * s_h * s_c

// Scratch (no allocations allowed -> __device__ globals, zero-initialized)
__device__ float g_h[(size_t)MAX_ROWS * D_IN];            // projected features (exact fp32)
__device__ signed char g_hb8[(size_t)MAX_ROWS * D_IN];    // int8 quantized h
__device__ signed char g_cbb8[(size_t)NUM_CODES * D_IN];  // int8 quantized codebook
__device__ float g_hsq[MAX_ROWS];                         // fl32(||h||^2)
__device__ float g_proj[(size_t)NUM_CODES * D_OUT];       // 0.25 * codebook @ head_w
__device__ float g_cbsq[NUM_CODES];                       // fl32(||codebook_c||^2)
__device__ int   g_cand[(size_t)MAX_ROWS * 16];           // 16 candidates per row

#define LDSM4(r0,r1,r2,r3,addr) \
    asm volatile("ldmatrix.sync.aligned.m8n8.x4.shared.b16 {%0,%1,%2,%3},[%4];" \
        : "=r"(r0), "=r"(r1), "=r"(r2), "=r"(r3) : "r"(addr))

// int8 MMA, base ISA: D(s32)[16x8] += A(s8)[16x32] * B(s8)[32x8]
#define IMMA16832(d, a, b) \
    asm volatile("mma.sync.aligned.m16n8k32.row.col.s32.s8.s8.s32 " \
        "{%0,%1,%2,%3},{%4,%5,%6,%7},{%8,%9},{%0,%1,%2,%3};" \
        : "+r"((d)[0]), "+r"((d)[1]), "+r"((d)[2]), "+r"((d)[3]) \
        : "r"((a)[0]), "r"((a)[1]), "r"((a)[2]), "r"((a)[3]), "r"((b)[0]), "r"((b)[1]))

__device__ __forceinline__ int q8(float v, float invs) {
    return __float2int_rn(fminf(fmaxf(v * invs, -127.f), 127.f));
}

// ---------------------------------------------------------------------------
// Kernel 1: h = x @ linear_proj   (M x 512) @ (512 x 512)
// EXACT bits (R4-proven): single fp32 accumulator per element, __fmaf_rn,
// k strictly ascending. Tile 64x64, BK=32, 256 threads, 4x4 per thread.
// Epilogue also emits int8-quantized h for the approximate pass.
// ---------------------------------------------------------------------------
__global__ __launch_bounds__(256) void k_gemm_xw(
    const float* __restrict__ A, const float* __restrict__ B, int M)
{
    __shared__ float sA[32][68];
    __shared__ float sB[32][68];

    const int tid = threadIdx.x;
    const int tx = tid & 15, ty = tid >> 4;
    const int row0 = blockIdx.x * 64;
    const int col0 = blockIdx.y * 64;

    float acc[4][4];
#pragma unroll
    for (int i = 0; i < 4; ++i)
#pragma unroll
        for (int j = 0; j < 4; ++j) acc[i][j] = 0.f;

    for (int kt = 0; kt < D_IN / 32; ++kt) {   // k tiles ascending
        __syncthreads();
#pragma unroll
        for (int i = 0; i < 2; ++i) {
            int e = tid + i * 256;
            int r = e >> 3, k4 = e & 7;
            float4 v = make_float4(0.f, 0.f, 0.f, 0.f);
            int gr = row0 + r;
            if (gr < M) v = *(const float4*)(A + (size_t)gr * D_IN + kt * 32 + k4 * 4);
            sA[k4 * 4 + 0][r] = v.x; sA[k4 * 4 + 1][r] = v.y;
            sA[k4 * 4 + 2][r] = v.z; sA[k4 * 4 + 3][r] = v.w;
        }
#pragma unroll
        for (int i = 0; i < 2; ++i) {
            int e = tid + i * 256;
            int k = e >> 4, n4 = e & 15;
            float4 v = *(const float4*)(B + (size_t)(kt * 32 + k) * D_IN + col0 + n4 * 4);
            *(float4*)&sB[k][n4 * 4] = v;
        }
        __syncthreads();
#pragma unroll
        for (int kk = 0; kk < 32; ++kk) {   // k ascending within tile
            float4 a = *(const float4*)&sA[kk][ty * 4];
            float4 b = *(const float4*)&sB[kk][tx * 4];
            float av[4] = {a.x, a.y, a.z, a.w};
            float bv[4] = {b.x, b.y, b.z, b.w};
#pragma unroll
            for (int i = 0; i < 4; ++i)
#pragma unroll
                for (int j = 0; j < 4; ++j)
                    acc[i][j] = __fmaf_rn(av[i], bv[j], acc[i][j]);
        }
    }
#pragma unroll
    for (int i = 0; i < 4; ++i) {
        int gr = row0 + ty * 4 + i;
        if (gr < M) {
            float4 v = make_float4(acc[i][0], acc[i][1], acc[i][2], acc[i][3]);
            *(float4*)(g_h + (size_t)gr * D_IN + col0 + tx * 4) = v;
            unsigned p0 = 0;
#pragma unroll
            for (int j = 0; j < 4; ++j)
                p0 |= ((unsigned)(q8(acc[i][j], INV_SH) & 255)) << (8 * j);
            *(unsigned*)(g_hb8 + (size_t)gr * D_IN + col0 + tx * 4) = p0;
        }
    }
}

// ---------------------------------------------------------------------------
// Kernel 2: row sum-of-squares (EXACT chain kept from R4).
// ---------------------------------------------------------------------------
__global__ void k_rowsq(const float* __restrict__ src, float* __restrict__ dst, int M)
{
    int warp = (blockIdx.x * blockDim.x + threadIdx.x) >> 5;
    int lane = threadIdx.x & 31;
    if (warp >= M) return;
    const float* p = src + (size_t)warp * D_IN;
    float s = 0.f;
#pragma unroll
    for (int j = 0; j < D_IN / 32; ++j) {
        float v = p[lane + j * 32];
        s = __fmaf_rn(v, v, s);
    }
#pragma unroll
    for (int off = 16; off; off >>= 1)
        s = __fadd_rn(s, __shfl_down_sync(0xffffffffu, s, off));
    if (lane == 0) dst[warp] = s;
}

// ---------------------------------------------------------------------------
// Kernel 3: codebook -> int8 (fixed scale)
// ---------------------------------------------------------------------------
__global__ void k_cbconv(const float* __restrict__ cb)
{
    int r = blockIdx.x;
    int k = threadIdx.x * 2;
    float v0 = cb[(size_t)r * D_IN + k];
    float v1 = cb[(size_t)r * D_IN + k + 1];
    unsigned short pk = (unsigned short)((q8(v0, INV_SC) & 255) | ((q8(v1, INV_SC) & 255) << 8));
    *(unsigned short*)(g_cbb8 + (size_t)r * D_IN + k) = pk;
}

// ---------------------------------------------------------------------------
// Kernel 4: proj = 0.25 * codebook @ head_w (value path only)
// ---------------------------------------------------------------------------
__global__ __launch_bounds__(256) void k_proj(
    const float* __restrict__ cb, const float* __restrict__ hw)
{
    __shared__ float scb[32][64];
    const int tid = threadIdx.x;
    const int c0 = blockIdx.x * 32;

    float acc[32];
#pragma unroll
    for (int r = 0; r < 32; ++r) acc[r] = 0.f;

    for (int kt = 0; kt < D_IN / 64; ++kt) {
        __syncthreads();
#pragma unroll
        for (int i = 0; i < 2; ++i) {
            int e = tid + i * 256;
            int r = e >> 4, k4 = e & 15;
            *(float4*)&scb[r][k4 * 4] =
                *(const float4*)(cb + (size_t)(c0 + r) * D_IN + kt * 64 + k4 * 4);
        }
        __syncthreads();
#pragma unroll 8
        for (int kk = 0; kk < 64; ++kk) {
            float w = hw[(size_t)(kt * 64 + kk) * D_OUT + tid];
#pragma unroll
            for (int r = 0; r < 32; ++r) acc[r] = __fmaf_rn(scb[r][kk], w, acc[r]);
        }
    }
#pragma unroll
    for (int r = 0; r < 32; ++r)
        g_proj[(size_t)(c0 + r) * D_OUT + tid] = 0.25f * acc[r];
}

// ---------------------------------------------------------------------------
// Kernel 5: approximate distance pass, int8 IMMA (m16n8k32, 2x HMMA rate).
// Block: 128 rows x 2048 codes (16 chunks of 128). Per row, 2 threads keep
// top-8 over their half -> 16 candidates. Exact rescore fixes ordering.
// (Selection-validated in R9: rel_err bit-identical to bf16 version.)
// ---------------------------------------------------------------------------
__global__ __launch_bounds__(256) void k_approx(int M)
{
    extern __shared__ char sm[];
    const unsigned sbase = (unsigned)__cvta_generic_to_shared(sm);
    const unsigned sBbase = sbase + 65536;
    float (*ssc)[132] = (float (*)[132])(sm + 98304);

    const int tid = threadIdx.x;
    const int lane = tid & 31;
    const int warp = tid >> 5;
    const int wm = warp & 3, wn = warp >> 2;
    const int row0 = blockIdx.x * 128;

    // A: 128 rows x 512 int8 = 512B rows, 32x16B units, swizzled u^(m&7)
#pragma unroll
    for (int it = 0; it < 16; ++it) {
        int idx = tid + it * 256;           // 0..4095
        int m = idx >> 5, u = idx & 31;
        uint4 v = ((const uint4*)g_hb8)[(size_t)(row0 + m) * 32 + u];
        *(uint4*)(sm + m * 512 + ((u ^ (m & 7)) << 4)) = v;
    }

    float tv[8]; int tix[8];
#pragma unroll
    for (int q = 0; q < 8; ++q) { tv[q] = 3.4e38f; tix[q] = 0; }

    for (int ch = 0; ch < 16; ++ch) {
        const int c0 = ch * 128;
        int d[2][8][4];
#pragma unroll
        for (int i = 0; i < 2; ++i)
#pragma unroll
            for (int j = 0; j < 8; ++j)
#pragma unroll
                for (int q = 0; q < 4; ++q) d[i][j][q] = 0;

        for (int kb = 0; kb < 2; ++kb) {     // 2 x 256B k-halves
            __syncthreads();
#pragma unroll
            for (int it = 0; it < 8; ++it) {
                int idx = tid + it * 256;
                int n = idx >> 4, u16 = idx & 15;
                uint4 v = ((const uint4*)g_cbb8)[(size_t)(c0 + n) * 32 + kb * 16 + u16];
                *(uint4*)(sm + 65536 + n * 256 + ((u16 ^ (n & 7)) << 4)) = v;
            }
            __syncthreads();
#pragma unroll
            for (int s = 0; s < 8; ++s) {    // 8 x 32B k-steps
                unsigned a[2][4], b[8][2];
                const int uA = kb * 16 + s * 2;
#pragma unroll
                for (int i = 0; i < 2; ++i) {
                    int rrow = wm * 32 + i * 16 + ((lane >> 3) & 1) * 8 + (lane & 7);
                    int un = uA + (lane >> 4);
                    unsigned ad = sbase + rrow * 512 + ((un ^ (rrow & 7)) << 4);
                    LDSM4(a[i][0], a[i][1], a[i][2], a[i][3], ad);
                }
#pragma unroll
                for (int jp = 0; jp < 4; ++jp) {
                    int nr = wn * 64 + jp * 16 + (lane >> 4) * 8 + (lane & 7);
                    int un = s * 2 + ((lane >> 3) & 1);
                    unsigned ad = sBbase + nr * 256 + ((un ^ (nr & 7)) << 4);
                    LDSM4(b[2 * jp][0], b[2 * jp][1], b[2 * jp + 1][0], b[2 * jp + 1][1], ad);
                }
#pragma unroll
                for (int i = 0; i < 2; ++i)
#pragma unroll
                    for (int j = 0; j < 8; ++j)
                        IMMA16832(d[i][j], a[i], b[j]);
            }
        }
        __syncthreads();
        {
            const int g = lane >> 2, t4 = lane & 3;
#pragma unroll
            for (int i = 0; i < 2; ++i) {
                int rb = wm * 32 + i * 16 + g;
#pragma unroll
                for (int j = 0; j < 8; ++j) {
                    int cw = wn * 64 + j * 8 + t4 * 2;
                    ssc[rb][cw]         = (float)d[i][j][0];
                    ssc[rb][cw + 1]     = (float)d[i][j][1];
                    ssc[rb + 8][cw]     = (float)d[i][j][2];
                    ssc[rb + 8][cw + 1] = (float)d[i][j][3];
                }
            }
        }
        __syncthreads();
        {
            const int srw = tid >> 1, shalf = tid & 1;
#pragma unroll 4
            for (int cc = 0; cc < 64; ++cc) {
                int c = shalf * 64 + cc;
                float s = __fmaf_rn(-SC2, ssc[srw][c], g_cbsq[c0 + c]);
                if (s < tv[7]) {
                    float v = s; int ii = c0 + c;
#pragma unroll
                    for (int q = 0; q < 8; ++q) {
                        if (v < tv[q]) {
                            float tvv = tv[q]; int tii = tix[q];
                            tv[q] = v; tix[q] = ii; v = tvv; ii = tii;
                        }
                    }
                }
            }
        }
    }

    const int srw = tid >> 1, shalf = tid & 1;
#pragma unroll
    for (int q = 0; q < 8; ++q)
        g_cand[(size_t)(row0 + srw) * 16 + shalf * 8 + q] = tix[q];
}

// ---------------------------------------------------------------------------
// Kernel 6: exact rescore of 16 candidates/row + top-4 + output.
// EXACT chain: sequential ascending-k __fmaf_rn dot; dist = fl(fl(hsq-2dot)+cbsq);
// rank by (dist_bits << 32 | index). One warp per row.
// ---------------------------------------------------------------------------
__global__ __launch_bounds__(256) void k_exact(
    const float* __restrict__ cb, const float* __restrict__ bias,
    float* __restrict__ out, int M)
{
    __shared__ float sh[8][D_IN];
    const int warp = threadIdx.x >> 5, lane = threadIdx.x & 31;
    const int row = blockIdx.x * 8 + warp;
    if (row >= M) return;

    float4* sh4 = (float4*)sh[warp];
    const float4* hrow = (const float4*)(g_h + (size_t)row * D_IN);
#pragma unroll
    for (int i = lane; i < D_IN / 4; i += 32) sh4[i] = hrow[i];
    __syncwarp();

    u64 key = 0xFFFFFFFFFFFFFFFFull;
    if (lane < 16) {
        int c = g_cand[(size_t)row * 16 + lane];
        const float4* crow = (const float4*)(cb + (size_t)c * D_IN);
        float acc = 0.f;
#pragma unroll 8
        for (int i = 0; i < D_IN / 4; ++i) {
            float4 hv = sh4[i];
            float4 cv = crow[i];
            acc = __fmaf_rn(hv.x, cv.x, acc);
            acc = __fmaf_rn(hv.y, cv.y, acc);
            acc = __fmaf_rn(hv.z, cv.z, acc);
            acc = __fmaf_rn(hv.w, cv.w, acc);
        }
        float t = __fmaf_rn(-2.0f, acc, g_hsq[row]);
        float dd = __fadd_rn(t, g_cbsq[c]);
        key = ((u64)__float_as_uint(dd) << 32) | (unsigned)c;
    }
    __syncwarp();

    int cq[4];
#pragma unroll
    for (int q = 0; q < 4; ++q) {
        u64 m = key;
#pragma unroll
        for (int off = 16; off; off >>= 1) {
            u64 o = __shfl_xor_sync(0xffffffffu, m, off);
            if (o < m) m = o;
        }
        cq[q] = (int)(m & 0xFFFFFFFFu);
        if (key == m) key = 0xFFFFFFFFFFFFFFFFull;
    }

#pragma unroll
    for (int j = 0; j < D_OUT / 32; ++j) {
        int col = lane + j * 32;
        float v = bias[col];
#pragma unroll
        for (int q = 0; q < 4; ++q)
            v += g_proj[(size_t)cq[q] * D_OUT + col];
        out[(size_t)row * D_OUT + col] = v;
    }
}

// ---------------------------------------------------------------------------
// Launch
// ---------------------------------------------------------------------------
extern "C" void kernel_launch(void* const* d_in, const int* in_sizes, int n_in,
                              void* d_out, int out_size)
{
    const float* x  = (const float*)d_in[0];   // [M, 512]
    const float* W  = (const float*)d_in[1];   // [512, 512]
    const float* cb = (const float*)d_in[2];   // [2048, 512]
    const float* hw = (const float*)d_in[3];   // [512, 256]
    const float* hb = (const float*)d_in[4];   // [256]
    float* out = (float*)d_out;                // [M, 256]

    const int M = in_sizes[0] / D_IN;
    const int mb  = (M + 63) / 64;
    const int mb2 = (M + 127) / 128;

    float* d_hsq;  cudaGetSymbolAddress((void**)&d_hsq,  g_hsq);
    float* d_cbsq; cudaGetSymbolAddress((void**)&d_cbsq, g_cbsq);
    float* d_hbuf; cudaGetSymbolAddress((void**)&d_hbuf, g_h);

    const int approx_smem = 65536 + 32768 + 128 * 132 * 4;  // 165888 B
    cudaFuncSetAttribute(k_approx, cudaFuncAttributeMaxDynamicSharedMemorySize,
                         approx_smem);

    k_gemm_xw<<<dim3(mb, D_IN / 64), 256>>>(x, W, M);
    k_rowsq<<<(M * 32 + 255) / 256, 256>>>(d_hbuf, d_hsq, M);
    k_rowsq<<<(NUM_CODES * 32) / 256, 256>>>(cb, d_cbsq, NUM_CODES);
    k_cbconv<<<NUM_CODES, 256>>>(cb);
    k_proj<<<NUM_CODES / 32, 256>>>(cb, hw);
    k_approx<<<mb2, 256, approx_smem>>>(M);
    k_exact<<<(M + 7) / 8, 256>>>(cb, hb, out, M);
}

// round 11
// speedup vs baseline: 1.3494x; 1.3494x over previous
#include <cuda_runtime.h>
#include <cuda_bf16.h>
#include <cstdint>
#include <cstring>

#define D_IN      512
#define NUM_CODES 2048
#define D_OUT     256
#define MAX_ROWS  100096   // ceil(100000/128)*128

typedef unsigned long long u64;

// Scratch (no allocations allowed -> __device__ globals, zero-initialized)
__device__ float g_h[(size_t)MAX_ROWS * D_IN];            // projected features (exact fp32)
__device__ __nv_bfloat16 g_hb[(size_t)MAX_ROWS * D_IN];   // bf16 copy of h
__device__ __nv_bfloat16 g_cbb[(size_t)NUM_CODES * D_IN]; // bf16 codebook
__device__ float g_hsq[MAX_ROWS];                         // fl32(||h||^2)
__device__ float g_proj[(size_t)NUM_CODES * D_OUT];       // 0.25 * codebook @ head_w
__device__ float g_cbsq[NUM_CODES];                       // fl32(||codebook_c||^2)
__device__ int   g_cand[(size_t)MAX_ROWS * 16];           // 16 candidates per row

#define LDSM4(r0,r1,r2,r3,addr) \
    asm volatile("ldmatrix.sync.aligned.m8n8.x4.shared.b16 {%0,%1,%2,%3},[%4];" \
        : "=r"(r0), "=r"(r1), "=r"(r2), "=r"(r3) : "r"(addr))

#define MMA16816(d, a, b) \
    asm volatile("mma.sync.aligned.m16n8k16.row.col.f32.bf16.bf16.f32 " \
        "{%0,%1,%2,%3},{%4,%5,%6,%7},{%8,%9},{%0,%1,%2,%3};" \
        : "+f"((d)[0]), "+f"((d)[1]), "+f"((d)[2]), "+f"((d)[3]) \
        : "r"((a)[0]), "r"((a)[1]), "r"((a)[2]), "r"((a)[3]), "r"((b)[0]), "r"((b)[1]))

__device__ __forceinline__ unsigned bf2u(__nv_bfloat162 v) {
    unsigned u; memcpy(&u, &v, 4); return u;
}

// ---------------------------------------------------------------------------
// Kernel 1: h = x @ linear_proj   (M x 512) @ (512 x 512)
// EXACT bits: single fp32 accumulator per element, __fmaf_rn, k strictly
// ascending (chain is tile-independent). Tile 128x128, BK=32, 256 threads,
// 8x8 per thread (R9-validated: faster than 64x64 and bit-identical).
// Epilogue also emits bf16 h for the approximate pass.
// ---------------------------------------------------------------------------
__global__ __launch_bounds__(256, 2) void k_gemm_xw(
    const float* __restrict__ A, const float* __restrict__ B, int M)
{
    __shared__ float sA[32][132];   // [k][m]
    __shared__ float sB[32][132];   // [k][n]

    const int tid = threadIdx.x;
    const int tx = tid & 15, ty = tid >> 4;
    const int row0 = blockIdx.x * 128;
    const int col0 = blockIdx.y * 128;

    float acc[8][8];
#pragma unroll
    for (int i = 0; i < 8; ++i)
#pragma unroll
        for (int j = 0; j < 8; ++j) acc[i][j] = 0.f;

    for (int kt = 0; kt < D_IN / 32; ++kt) {   // k tiles ascending
        __syncthreads();
        // A tile: 128 rows x 32 k -> sA[k][m]
#pragma unroll
        for (int i = 0; i < 4; ++i) {
            int e = tid + i * 256;          // 0..1023
            int r = e >> 3, k4 = e & 7;
            float4 v = make_float4(0.f, 0.f, 0.f, 0.f);
            int gr = row0 + r;
            if (gr < M) v = *(const float4*)(A + (size_t)gr * D_IN + kt * 32 + k4 * 4);
            sA[k4 * 4 + 0][r] = v.x; sA[k4 * 4 + 1][r] = v.y;
            sA[k4 * 4 + 2][r] = v.z; sA[k4 * 4 + 3][r] = v.w;
        }
        // B tile: 32 k x 128 n
#pragma unroll
        for (int i = 0; i < 4; ++i) {
            int e = tid + i * 256;          // 0..1023
            int k = e >> 5, n4 = e & 31;
            float4 v = *(const float4*)(B + (size_t)(kt * 32 + k) * D_IN + col0 + n4 * 4);
            *(float4*)&sB[k][n4 * 4] = v;
        }
        __syncthreads();
#pragma unroll
        for (int kk = 0; kk < 32; ++kk) {   // k ascending within tile
            float a[8], b[8];
            *(float4*)&a[0] = *(const float4*)&sA[kk][ty * 8];
            *(float4*)&a[4] = *(const float4*)&sA[kk][ty * 8 + 4];
            *(float4*)&b[0] = *(const float4*)&sB[kk][tx * 8];
            *(float4*)&b[4] = *(const float4*)&sB[kk][tx * 8 + 4];
#pragma unroll
            for (int i = 0; i < 8; ++i)
#pragma unroll
                for (int j = 0; j < 8; ++j)
                    acc[i][j] = __fmaf_rn(a[i], b[j], acc[i][j]);
        }
    }
#pragma unroll
    for (int i = 0; i < 8; ++i) {
        int gr = row0 + ty * 8 + i;
        if (gr < M) {
            float* hp = g_h + (size_t)gr * D_IN + col0 + tx * 8;
            *(float4*)hp       = make_float4(acc[i][0], acc[i][1], acc[i][2], acc[i][3]);
            *(float4*)(hp + 4) = make_float4(acc[i][4], acc[i][5], acc[i][6], acc[i][7]);
            uint4 bb;
            bb.x = bf2u(__floats2bfloat162_rn(acc[i][0], acc[i][1]));
            bb.y = bf2u(__floats2bfloat162_rn(acc[i][2], acc[i][3]));
            bb.z = bf2u(__floats2bfloat162_rn(acc[i][4], acc[i][5]));
            bb.w = bf2u(__floats2bfloat162_rn(acc[i][6], acc[i][7]));
            *(uint4*)(g_hb + (size_t)gr * D_IN + col0 + tx * 8) = bb;
        }
    }
}

// ---------------------------------------------------------------------------
// Kernel 2: row sum-of-squares (EXACT chain kept from R4).
// ---------------------------------------------------------------------------
__global__ void k_rowsq(const float* __restrict__ src, float* __restrict__ dst, int M)
{
    int warp = (blockIdx.x * blockDim.x + threadIdx.x) >> 5;
    int lane = threadIdx.x & 31;
    if (warp >= M) return;
    const float* p = src + (size_t)warp * D_IN;
    float s = 0.f;
#pragma unroll
    for (int j = 0; j < D_IN / 32; ++j) {
        float v = p[lane + j * 32];
        s = __fmaf_rn(v, v, s);
    }
#pragma unroll
    for (int off = 16; off; off >>= 1)
        s = __fadd_rn(s, __shfl_down_sync(0xffffffffu, s, off));
    if (lane == 0) dst[warp] = s;
}

// ---------------------------------------------------------------------------
// Kernel 3: codebook -> bf16
// ---------------------------------------------------------------------------
__global__ void k_cbconv(const float* __restrict__ cb)
{
    int r = blockIdx.x;
    for (int k = threadIdx.x; k < D_IN; k += blockDim.x)
        g_cbb[(size_t)r * D_IN + k] = __float2bfloat16_rn(cb[(size_t)r * D_IN + k]);
}

// ---------------------------------------------------------------------------
// Kernel 4: proj = 0.25 * codebook @ head_w (value path only)
// ---------------------------------------------------------------------------
__global__ __launch_bounds__(256) void k_proj(
    const float* __restrict__ cb, const float* __restrict__ hw)
{
    __shared__ float scb[32][64];
    const int tid = threadIdx.x;
    const int c0 = blockIdx.x * 32;

    float acc[32];
#pragma unroll
    for (int r = 0; r < 32; ++r) acc[r] = 0.f;

    for (int kt = 0; kt < D_IN / 64; ++kt) {
        __syncthreads();
#pragma unroll
        for (int i = 0; i < 2; ++i) {
            int e = tid + i * 256;
            int r = e >> 4, k4 = e & 15;
            *(float4*)&scb[r][k4 * 4] =
                *(const float4*)(cb + (size_t)(c0 + r) * D_IN + kt * 64 + k4 * 4);
        }
        __syncthreads();
#pragma unroll 8
        for (int kk = 0; kk < 64; ++kk) {
            float w = hw[(size_t)(kt * 64 + kk) * D_OUT + tid];
#pragma unroll
            for (int r = 0; r < 32; ++r) acc[r] = __fmaf_rn(scb[r][kk], w, acc[r]);
        }
    }
#pragma unroll
    for (int r = 0; r < 32; ++r)
        g_proj[(size_t)(c0 + r) * D_OUT + tid] = 0.25f * acc[r];
}

// ---------------------------------------------------------------------------
// Kernel 5: approximate distance pass on tensor cores (bf16 HMMA, base ISA).
// Block: 128 rows x 2048 codes (16 chunks of 128), 256 threads / 8 warps.
// Warp tile 32m x 64n. Per row, 2 threads each keep top-8 over their half
// -> 16 candidates. (R5-validated version, unchanged.)
// ---------------------------------------------------------------------------
__global__ __launch_bounds__(256) void k_approx(int M)
{
    extern __shared__ char sm[];
    const unsigned sbase = (unsigned)__cvta_generic_to_shared(sm);
    const unsigned sBbase = sbase + 131072;
    float (*ssc)[132] = (float (*)[132])(sm + 163840);

    const int tid = threadIdx.x;
    const int lane = tid & 31;
    const int warp = tid >> 5;
    const int wm = warp & 3, wn = warp >> 2;
    const int row0 = blockIdx.x * 128;

#pragma unroll
    for (int it = 0; it < 32; ++it) {
        int idx = tid + it * 256;
        int m = idx >> 6, u = idx & 63;
        uint4 v = ((const uint4*)g_hb)[(size_t)(row0 + m) * 64 + u];
        *(uint4*)(sm + m * 1024 + ((u ^ (m & 7)) << 4)) = v;
    }

    float tv[8]; int tix[8];
#pragma unroll
    for (int q = 0; q < 8; ++q) { tv[q] = 3.4e38f; tix[q] = 0; }

    for (int ch = 0; ch < 16; ++ch) {
        const int c0 = ch * 128;
        float d[2][8][4];
#pragma unroll
        for (int i = 0; i < 2; ++i)
#pragma unroll
            for (int j = 0; j < 8; ++j)
#pragma unroll
                for (int q = 0; q < 4; ++q) d[i][j][q] = 0.f;

        for (int kb = 0; kb < 512; kb += 128) {
            __syncthreads();
#pragma unroll
            for (int it = 0; it < 8; ++it) {
                int idx = tid + it * 256;
                int n = idx >> 4, u16 = idx & 15;
                uint4 v = ((const uint4*)g_cbb)[(size_t)(c0 + n) * 64 + (kb >> 3) + u16];
                *(uint4*)(sm + 131072 + n * 256 + ((u16 ^ (n & 7)) << 4)) = v;
            }
            __syncthreads();
#pragma unroll
            for (int s = 0; s < 8; ++s) {
                unsigned a[2][4], b[8][2];
                const int uA = (kb >> 3) + s * 2;
#pragma unroll
                for (int i = 0; i < 2; ++i) {
                    int rrow = wm * 32 + i * 16 + ((lane >> 3) & 1) * 8 + (lane & 7);
                    int un = uA + (lane >> 4);
                    unsigned ad = sbase + rrow * 1024 + ((un ^ (rrow & 7)) << 4);
                    LDSM4(a[i][0], a[i][1], a[i][2], a[i][3], ad);
                }
#pragma unroll
                for (int jp = 0; jp < 4; ++jp) {
                    int nr = wn * 64 + jp * 16 + (lane >> 4) * 8 + (lane & 7);
                    int un = s * 2 + ((lane >> 3) & 1);
                    unsigned ad = sBbase + nr * 256 + ((un ^ (nr & 7)) << 4);
                    LDSM4(b[2 * jp][0], b[2 * jp][1], b[2 * jp + 1][0], b[2 * jp + 1][1], ad);
                }
#pragma unroll
                for (int i = 0; i < 2; ++i)
#pragma unroll
                    for (int j = 0; j < 8; ++j)
                        MMA16816(d[i][j], a[i], b[j]);
            }
        }
        __syncthreads();
        {
            const int g = lane >> 2, t4 = lane & 3;
#pragma unroll
            for (int i = 0; i < 2; ++i) {
                int rb = wm * 32 + i * 16 + g;
#pragma unroll
                for (int j = 0; j < 8; ++j) {
                    int cw = wn * 64 + j * 8 + t4 * 2;
                    ssc[rb][cw]         = d[i][j][0];
                    ssc[rb][cw + 1]     = d[i][j][1];
                    ssc[rb + 8][cw]     = d[i][j][2];
                    ssc[rb + 8][cw + 1] = d[i][j][3];
                }
            }
        }
        __syncthreads();
        {
            const int srw = tid >> 1, shalf = tid & 1;
#pragma unroll 4
            for (int cc = 0; cc < 64; ++cc) {
                int c = shalf * 64 + cc;
                float s = __fmaf_rn(-2.f, ssc[srw][c], g_cbsq[c0 + c]);
                if (s < tv[7]) {
                    float v = s; int ii = c0 + c;
#pragma unroll
                    for (int q = 0; q < 8; ++q) {
                        if (v < tv[q]) {
                            float tvv = tv[q]; int tii = tix[q];
                            tv[q] = v; tix[q] = ii; v = tvv; ii = tii;
                        }
                    }
                }
            }
        }
    }

    const int srw = tid >> 1, shalf = tid & 1;
#pragma unroll
    for (int q = 0; q < 8; ++q)
        g_cand[(size_t)(row0 + srw) * 16 + shalf * 8 + q] = tix[q];
}

// ---------------------------------------------------------------------------
// Kernel 6: exact rescore of 16 candidates/row + top-4 + output.
// EXACT chain: sequential ascending-k __fmaf_rn dot; dist = fl(fl(hsq-2dot)+cbsq);
// rank by (dist_bits << 32 | index). One warp per row.
// ---------------------------------------------------------------------------
__global__ __launch_bounds__(256) void k_exact(
    const float* __restrict__ cb, const float* __restrict__ bias,
    float* __restrict__ out, int M)
{
    __shared__ float sh[8][D_IN];
    const int warp = threadIdx.x >> 5, lane = threadIdx.x & 31;
    const int row = blockIdx.x * 8 + warp;
    if (row >= M) return;

    float4* sh4 = (float4*)sh[warp];
    const float4* hrow = (const float4*)(g_h + (size_t)row * D_IN);
#pragma unroll
    for (int i = lane; i < D_IN / 4; i += 32) sh4[i] = hrow[i];
    __syncwarp();

    u64 key = 0xFFFFFFFFFFFFFFFFull;
    if (lane < 16) {
        int c = g_cand[(size_t)row * 16 + lane];
        const float4* crow = (const float4*)(cb + (size_t)c * D_IN);
        float acc = 0.f;
#pragma unroll 8
        for (int i = 0; i < D_IN / 4; ++i) {
            float4 hv = sh4[i];
            float4 cv = crow[i];
            acc = __fmaf_rn(hv.x, cv.x, acc);
            acc = __fmaf_rn(hv.y, cv.y, acc);
            acc = __fmaf_rn(hv.z, cv.z, acc);
            acc = __fmaf_rn(hv.w, cv.w, acc);
        }
        float t = __fmaf_rn(-2.0f, acc, g_hsq[row]);
        float dd = __fadd_rn(t, g_cbsq[c]);
        key = ((u64)__float_as_uint(dd) << 32) | (unsigned)c;
    }
    __syncwarp();

    int cq[4];
#pragma unroll
    for (int q = 0; q < 4; ++q) {
        u64 m = key;
#pragma unroll
        for (int off = 16; off; off >>= 1) {
            u64 o = __shfl_xor_sync(0xffffffffu, m, off);
            if (o < m) m = o;
        }
        cq[q] = (int)(m & 0xFFFFFFFFu);
        if (key == m) key = 0xFFFFFFFFFFFFFFFFull;
    }

#pragma unroll
    for (int j = 0; j < D_OUT / 32; ++j) {
        int col = lane + j * 32;
        float v = bias[col];
#pragma unroll
        for (int q = 0; q < 4; ++q)
            v += g_proj[(size_t)cq[q] * D_OUT + col];
        out[(size_t)row * D_OUT + col] = v;
    }
}

// ---------------------------------------------------------------------------
// Launch
// ---------------------------------------------------------------------------
extern "C" void kernel_launch(void* const* d_in, const int* in_sizes, int n_in,
                              void* d_out, int out_size)
{
    const float* x  = (const float*)d_in[0];   // [M, 512]
    const float* W  = (const float*)d_in[1];   // [512, 512]
    const float* cb = (const float*)d_in[2];   // [2048, 512]
    const float* hw = (const float*)d_in[3];   // [512, 256]
    const float* hb = (const float*)d_in[4];   // [256]
    float* out = (float*)d_out;                // [M, 256]

    const int M = in_sizes[0] / D_IN;
    const int mb2 = (M + 127) / 128;

    float* d_hsq;  cudaGetSymbolAddress((void**)&d_hsq,  g_hsq);
    float* d_cbsq; cudaGetSymbolAddress((void**)&d_cbsq, g_cbsq);
    float* d_hbuf; cudaGetSymbolAddress((void**)&d_hbuf, g_h);

    const int approx_smem = 131072 + 32768 + 128 * 132 * 4;  // 231424 B
    cudaFuncSetAttribute(k_approx, cudaFuncAttributeMaxDynamicSharedMemorySize,
                         approx_smem);

    k_gemm_xw<<<dim3(mb2, 4), 256>>>(x, W, M);
    k_rowsq<<<(M * 32 + 255) / 256, 256>>>(d_hbuf, d_hsq, M);
    k_rowsq<<<(NUM_CODES * 32) / 256, 256>>>(cb, d_cbsq, NUM_CODES);
    k_cbconv<<<NUM_CODES, 256>>>(cb);
    k_proj<<<NUM_CODES / 32, 256>>>(cb, hw);
    k_approx<<<mb2, 256, approx_smem>>>(M);
    k_exact<<<(M + 7) / 8, 256>>>(cb, hb, out, M);
}